// round 5
// baseline (speedup 1.0000x reference)
#include <cuda_runtime.h>

#define NP 16384   // N_POINTS
#define NS 8192    // N_SAMPLES
#define KCHUNK 256
#define NKCH (NS / KCHUNK)   // 32 k-chunks
#define TPB 256
#define IPT 4
#define IBLK (TPB * IPT)     // 1024 i-points per tile
#define NIB (NS / IBLK)      // 8 i-tiles

typedef unsigned long long u64;

// Scratch (no device allocations allowed). Counters are self-resetting:
// every kernel run starts and ends with them at zero (graph-replay safe).
__device__ float    g_partial[NKCH * NS];  // [kchunk][i] partial mins (incl ||a||^2)
__device__ float    g_tile_sum[NIB];
__device__ unsigned g_tile_ctr[NIB];       // static zero-init
__device__ unsigned g_done_ctr;            // static zero-init

__device__ __forceinline__ u64 pack2(float lo, float hi) {
    u64 r;
    asm("mov.b64 %0, {%1, %2};" : "=l"(r) : "f"(lo), "f"(hi));
    return r;
}
__device__ __forceinline__ void unpack2(u64 v, float& lo, float& hi) {
    asm("mov.b64 {%0, %1}, %2;" : "=f"(lo), "=f"(hi) : "l"(v));
}
__device__ __forceinline__ u64 fma2(u64 a, u64 b, u64 c) {
    u64 d;
    asm("fma.rn.f32x2 %0, %1, %2, %3;" : "=l"(d) : "l"(a), "l"(b), "l"(c));
    return d;
}

__global__ __launch_bounds__(TPB) void chamfer_kernel(
    const float* __restrict__ a, const float* __restrict__ b,
    const int* __restrict__ a_idx, const int* __restrict__ b_idx,
    float* __restrict__ out)
{
    // SoA so two consecutive k's load as one broadcast LDS.64
    __shared__ __align__(8) float sbx[KCHUNK], sby[KCHUNK], sbz[KCHUNK], sbw[KCHUNK];
    __shared__ float ssum[TPB / 32];
    __shared__ int s_last;

    const int t = threadIdx.x;
    const int it = blockIdx.x;   // i-tile 0..NIB-1
    const int kq = blockIdx.y;   // k-chunk 0..NKCH-1
    const int ibase = it * IBLK + t;

    // ---- gather this block's 256 b-points: (-2bx,-2by,-2bz,||b||^2) ----
    {
        int ib = b_idx[kq * KCHUNK + t];
        float bx = b[ib], by = b[NP + ib], bz = b[2 * NP + ib];
        sbx[t] = -2.0f * bx; sby[t] = -2.0f * by; sbz[t] = -2.0f * bz;
        sbw[t] = bx * bx + by * by + bz * bz;
    }

    // ---- gather this thread's 4 a-points ----
    u64 ax2[IPT], ay2[IPT], az2[IPT];
    float sqa[IPT], mn_e[IPT], mn_o[IPT];
    #pragma unroll
    for (int r = 0; r < IPT; r++) {
        int ia = a_idx[ibase + r * TPB];
        float ax = a[ia], ay = a[NP + ia], az = a[2 * NP + ia];
        ax2[r] = pack2(ax, ax);
        ay2[r] = pack2(ay, ay);
        az2[r] = pack2(az, az);
        sqa[r] = ax * ax + ay * ay + az * az;
        mn_e[r] = 3.4e38f; mn_o[r] = 3.4e38f;
    }
    __syncthreads();

    // ---- mainloop: packed over two k's per issue slot ----
    #pragma unroll 4
    for (int k = 0; k < KCHUNK; k += 2) {
        u64 bx2 = *reinterpret_cast<const u64*>(&sbx[k]);
        u64 by2 = *reinterpret_cast<const u64*>(&sby[k]);
        u64 bz2 = *reinterpret_cast<const u64*>(&sbz[k]);
        u64 bw2 = *reinterpret_cast<const u64*>(&sbw[k]);
        #pragma unroll
        for (int r = 0; r < IPT; r++) {
            // ||b||^2 - 2 b.a   (||a||^2 added below; two k's per fma2)
            u64 d2 = fma2(bx2, ax2[r], fma2(by2, ay2[r], fma2(bz2, az2[r], bw2)));
            float dl, dh;
            unpack2(d2, dl, dh);
            mn_e[r] = fminf(mn_e[r], dl);
            mn_o[r] = fminf(mn_o[r], dh);
        }
    }

    #pragma unroll
    for (int r = 0; r < IPT; r++)
        g_partial[kq * NS + ibase + r * TPB] = fminf(mn_e[r], mn_o[r]) + sqa[r];

    // ---- completion: last block of this i-tile reduces the tile ----
    __threadfence();
    __syncthreads();
    if (t == 0) {
        unsigned old = atomicAdd(&g_tile_ctr[it], 1u);
        s_last = (old == NKCH - 1);
    }
    __syncthreads();
    if (!s_last) return;

    __threadfence();  // order our partial-reads after the counter acquire
    float v = 0.0f;
    #pragma unroll
    for (int r = 0; r < IPT; r++) {
        int i = ibase + r * TPB;
        float m = g_partial[i];
        #pragma unroll
        for (int c = 1; c < NKCH; c++)
            m = fminf(m, g_partial[c * NS + i]);
        v += m;
    }
    // block-wide sum
    #pragma unroll
    for (int o = 16; o > 0; o >>= 1)
        v += __shfl_down_sync(0xffffffffu, v, o);
    if ((t & 31) == 0) ssum[t >> 5] = v;
    __syncthreads();
    if (t == 0) {
        float s = 0.0f;
        #pragma unroll
        for (int w = 0; w < TPB / 32; w++) s += ssum[w];
        g_tile_sum[it] = s;
        g_tile_ctr[it] = 0;            // reset for next replay
        __threadfence();
        unsigned old = atomicAdd(&g_done_ctr, 1u);
        if (old == NIB - 1) {
            __threadfence();
            float tot = 0.0f;
            #pragma unroll
            for (int j = 0; j < NIB; j++) tot += g_tile_sum[j];  // fixed order
            *out = tot;
            g_done_ctr = 0;            // reset for next replay
        }
    }
}

extern "C" void kernel_launch(void* const* d_in, const int* in_sizes, int n_in,
                              void* d_out, int out_size) {
    const float* a  = (const float*)d_in[0];
    const float* b  = (const float*)d_in[1];
    const int*   ai = (const int*)d_in[2];
    const int*   bi = (const int*)d_in[3];
    float* out = (float*)d_out;

    chamfer_kernel<<<dim3(NIB, NKCH), TPB>>>(a, b, ai, bi, out);
}

// round 6
// speedup vs baseline: 1.0672x; 1.0672x over previous
#include <cuda_runtime.h>

#define NP 16384   // N_POINTS
#define NS 8192    // N_SAMPLES
#define KCHUNK 256
#define NKCH (NS / KCHUNK)   // 32 k-chunks
#define TPB 256
#define IPT 4
#define IBLK (TPB * IPT)     // 1024 i-points per tile
#define NIB (NS / IBLK)      // 8 i-tiles

typedef unsigned long long u64;

// Scratch (no device allocations). Counters self-reset each run (graph-safe).
__device__ float4   g_a[NS];               // (ax, ay, az, ||a||^2)
__device__ float4   g_b[NS];               // (-2bx, -2by, -2bz, ||b||^2)
__device__ float    g_partial[NKCH * NS];  // [kchunk][i] partial mins
__device__ unsigned g_tile_ctr[NIB];       // static zero-init

__device__ __forceinline__ u64 pack2(float lo, float hi) {
    u64 r;
    asm("mov.b64 %0, {%1, %2};" : "=l"(r) : "f"(lo), "f"(hi));
    return r;
}
__device__ __forceinline__ void unpack2(u64 v, float& lo, float& hi) {
    asm("mov.b64 {%0, %1}, %2;" : "=f"(lo), "=f"(hi) : "l"(v));
}
__device__ __forceinline__ u64 fma2(u64 a, u64 b, u64 c) {
    u64 d;
    asm("fma.rn.f32x2 %0, %1, %2, %3;" : "=l"(d) : "l"(a), "l"(b), "l"(c));
    return d;
}

__global__ void gather_kernel(const float* __restrict__ a,
                              const float* __restrict__ b,
                              const int* __restrict__ a_idx,
                              const int* __restrict__ b_idx,
                              float* __restrict__ out) {
    int i = blockIdx.x * blockDim.x + threadIdx.x;
    if (i == 0) *out = 0.0f;   // d_out is poisoned; reducers atomicAdd into it
    if (i >= NS) return;

    int ia = a_idx[i];
    float ax = a[ia], ay = a[NP + ia], az = a[2 * NP + ia];
    g_a[i] = make_float4(ax, ay, az, ax * ax + ay * ay + az * az);

    int ib = b_idx[i];
    float bx = b[ib], by = b[NP + ib], bz = b[2 * NP + ib];
    g_b[i] = make_float4(-2.0f * bx, -2.0f * by, -2.0f * bz,
                         bx * bx + by * by + bz * bz);
}

__global__ __launch_bounds__(TPB) void dist_kernel(float* __restrict__ out) {
    // SoA so two consecutive k's load as one broadcast LDS.64
    __shared__ __align__(8) float sbx[KCHUNK], sby[KCHUNK], sbz[KCHUNK], sbw[KCHUNK];
    __shared__ float ssum[TPB / 32];
    __shared__ int s_last;

    const int t = threadIdx.x;
    const int it = blockIdx.x;   // i-tile
    const int kq = blockIdx.y;   // k-chunk
    const int ibase = it * IBLK + t;

    {   // coalesced packed-b stage
        float4 v = g_b[kq * KCHUNK + t];
        sbx[t] = v.x; sby[t] = v.y; sbz[t] = v.z; sbw[t] = v.w;
    }

    u64 ax2[IPT], ay2[IPT], az2[IPT];
    float sqa[IPT], mn_e[IPT], mn_o[IPT];
    #pragma unroll
    for (int r = 0; r < IPT; r++) {       // coalesced packed-a loads
        float4 v = g_a[ibase + r * TPB];
        ax2[r] = pack2(v.x, v.x);
        ay2[r] = pack2(v.y, v.y);
        az2[r] = pack2(v.z, v.z);
        sqa[r] = v.w;
        mn_e[r] = 3.4e38f; mn_o[r] = 3.4e38f;
    }
    __syncthreads();

    #pragma unroll 4
    for (int k = 0; k < KCHUNK; k += 2) {
        u64 bx2 = *reinterpret_cast<const u64*>(&sbx[k]);
        u64 by2 = *reinterpret_cast<const u64*>(&sby[k]);
        u64 bz2 = *reinterpret_cast<const u64*>(&sbz[k]);
        u64 bw2 = *reinterpret_cast<const u64*>(&sbw[k]);
        #pragma unroll
        for (int r = 0; r < IPT; r++) {
            // two k's at once: ||b||^2 - 2 b.a  (||a||^2 added at the end)
            u64 d2 = fma2(bx2, ax2[r], fma2(by2, ay2[r], fma2(bz2, az2[r], bw2)));
            float dl, dh;
            unpack2(d2, dl, dh);
            mn_e[r] = fminf(mn_e[r], dl);
            mn_o[r] = fminf(mn_o[r], dh);
        }
    }

    #pragma unroll
    for (int r = 0; r < IPT; r++)   // coalesced partial writes
        g_partial[kq * NS + ibase + r * TPB] = fminf(mn_e[r], mn_o[r]) + sqa[r];

    // ---- last block of this i-tile reduces the tile and adds to out ----
    __threadfence();
    __syncthreads();
    if (t == 0) {
        unsigned old = atomicAdd(&g_tile_ctr[it], 1u);
        s_last = (old == NKCH - 1);
    }
    __syncthreads();
    if (!s_last) return;

    __threadfence();
    float v = 0.0f;
    #pragma unroll
    for (int r = 0; r < IPT; r++) {
        int i = ibase + r * TPB;
        float m = g_partial[i];
        #pragma unroll
        for (int c = 1; c < NKCH; c++)     // 32 independent LDGs, high MLP
            m = fminf(m, g_partial[c * NS + i]);
        v += m;
    }
    #pragma unroll
    for (int o = 16; o > 0; o >>= 1)
        v += __shfl_down_sync(0xffffffffu, v, o);
    if ((t & 31) == 0) ssum[t >> 5] = v;
    __syncthreads();
    if (t == 0) {
        float s = 0.0f;
        #pragma unroll
        for (int w = 0; w < TPB / 32; w++) s += ssum[w];
        g_tile_ctr[it] = 0;         // reset for next graph replay
        atomicAdd(out, s);
    }
}

extern "C" void kernel_launch(void* const* d_in, const int* in_sizes, int n_in,
                              void* d_out, int out_size) {
    const float* a  = (const float*)d_in[0];
    const float* b  = (const float*)d_in[1];
    const int*   ai = (const int*)d_in[2];
    const int*   bi = (const int*)d_in[3];
    float* out = (float*)d_out;

    gather_kernel<<<(NS + 255) / 256, 256>>>(a, b, ai, bi, out);
    dist_kernel<<<dim3(NIB, NKCH), TPB>>>(out);
}

// round 11
// speedup vs baseline: 1.5976x; 1.4970x over previous
#include <cuda_runtime.h>

#define NP 16384   // N_POINTS
#define NS 8192    // N_SAMPLES
#define KCHUNK 256
#define NKCH (NS / KCHUNK)   // 32 k-chunks
#define TPB 256
#define IPT 2
#define IBLK (TPB * IPT)     // 512 i-points per tile
#define NIB (NS / IBLK)      // 16 i-tiles -> grid 512

typedef unsigned long long u64;

// Scratch (no device allocations). Counters self-reset each run (graph-safe).
__device__ float4   g_a[NS];               // (ax, ay, az, ||a||^2)
__device__ float4   g_b[NS];               // (-2bx, -2by, -2bz, ||b||^2)
__device__ float    g_partial[NKCH * NS];  // [kchunk][i] partial mins
__device__ unsigned g_tile_ctr[NIB];       // static zero-init

__device__ __forceinline__ u64 pack2(float lo, float hi) {
    u64 r;
    asm("mov.b64 %0, {%1, %2};" : "=l"(r) : "f"(lo), "f"(hi));
    return r;
}
__device__ __forceinline__ void unpack2(u64 v, float& lo, float& hi) {
    asm("mov.b64 {%0, %1}, %2;" : "=f"(lo), "=f"(hi) : "l"(v));
}
__device__ __forceinline__ u64 fma2(u64 a, u64 b, u64 c) {
    u64 d;
    asm("fma.rn.f32x2 %0, %1, %2, %3;" : "=l"(d) : "l"(a), "l"(b), "l"(c));
    return d;
}

__global__ void gather_kernel(const float* __restrict__ a,
                              const float* __restrict__ b,
                              const int* __restrict__ a_idx,
                              const int* __restrict__ b_idx,
                              float* __restrict__ out) {
    int i = blockIdx.x * blockDim.x + threadIdx.x;
    if (i == 0) *out = 0.0f;   // d_out is poisoned; reducers atomicAdd into it
    if (i >= NS) return;

    int ia = a_idx[i];
    float ax = a[ia], ay = a[NP + ia], az = a[2 * NP + ia];
    g_a[i] = make_float4(ax, ay, az, ax * ax + ay * ay + az * az);

    int ib = b_idx[i];
    float bx = b[ib], by = b[NP + ib], bz = b[2 * NP + ib];
    g_b[i] = make_float4(-2.0f * bx, -2.0f * by, -2.0f * bz,
                         bx * bx + by * by + bz * bz);
}

__global__ __launch_bounds__(TPB, 4) void dist_kernel(float* __restrict__ out) {
    // SoA so two consecutive k's load as one broadcast LDS.64
    __shared__ __align__(8) float sbx[KCHUNK], sby[KCHUNK], sbz[KCHUNK], sbw[KCHUNK];
    __shared__ float ssum[TPB / 32];
    __shared__ int s_last;

    const int t = threadIdx.x;
    const int it = blockIdx.x;   // i-tile 0..NIB-1
    const int kq = blockIdx.y;   // k-chunk 0..NKCH-1
    const int ibase = it * IBLK + t;

    {   // coalesced packed-b stage
        float4 v = g_b[kq * KCHUNK + t];
        sbx[t] = v.x; sby[t] = v.y; sbz[t] = v.z; sbw[t] = v.w;
    }

    u64 ax2[IPT], ay2[IPT], az2[IPT];
    float sqa[IPT], mn_e[IPT], mn_o[IPT];
    #pragma unroll
    for (int r = 0; r < IPT; r++) {       // coalesced packed-a loads
        float4 v = g_a[ibase + r * TPB];
        ax2[r] = pack2(v.x, v.x);
        ay2[r] = pack2(v.y, v.y);
        az2[r] = pack2(v.z, v.z);
        sqa[r] = v.w;
        mn_e[r] = 3.4e38f; mn_o[r] = 3.4e38f;
    }
    __syncthreads();

    #pragma unroll 8
    for (int k = 0; k < KCHUNK; k += 2) {
        u64 bx2 = *reinterpret_cast<const u64*>(&sbx[k]);
        u64 by2 = *reinterpret_cast<const u64*>(&sby[k]);
        u64 bz2 = *reinterpret_cast<const u64*>(&sbz[k]);
        u64 bw2 = *reinterpret_cast<const u64*>(&sbw[k]);
        #pragma unroll
        for (int r = 0; r < IPT; r++) {
            // two k's at once: ||b||^2 - 2 b.a  (||a||^2 added at the end)
            u64 d2 = fma2(bx2, ax2[r], fma2(by2, ay2[r], fma2(bz2, az2[r], bw2)));
            float dl, dh;
            unpack2(d2, dl, dh);
            mn_e[r] = fminf(mn_e[r], dl);
            mn_o[r] = fminf(mn_o[r], dh);
        }
    }

    #pragma unroll
    for (int r = 0; r < IPT; r++)   // coalesced partial writes
        g_partial[kq * NS + ibase + r * TPB] = fminf(mn_e[r], mn_o[r]) + sqa[r];

    // ---- last block of this i-tile reduces the tile and adds to out ----
    __threadfence();
    __syncthreads();
    if (t == 0) {
        unsigned old = atomicAdd(&g_tile_ctr[it], 1u);
        s_last = (old == NKCH - 1);
    }
    __syncthreads();
    if (!s_last) return;

    __threadfence();
    float v = 0.0f;
    #pragma unroll
    for (int r = 0; r < IPT; r++) {
        int i = ibase + r * TPB;
        float m = g_partial[i];
        #pragma unroll
        for (int c = 1; c < NKCH; c++)     // 32 independent LDGs, high MLP
            m = fminf(m, g_partial[c * NS + i]);
        v += m;
    }
    #pragma unroll
    for (int o = 16; o > 0; o >>= 1)
        v += __shfl_down_sync(0xffffffffu, v, o);
    if ((t & 31) == 0) ssum[t >> 5] = v;
    __syncthreads();
    if (t == 0) {
        float s = 0.0f;
        #pragma unroll
        for (int w = 0; w < TPB / 32; w++) s += ssum[w];
        g_tile_ctr[it] = 0;         // reset for next graph replay
        atomicAdd(out, s);
    }
}

extern "C" void kernel_launch(void* const* d_in, const int* in_sizes, int n_in,
                              void* d_out, int out_size) {
    const float* a  = (const float*)d_in[0];
    const float* b  = (const float*)d_in[1];
    const int*   ai = (const int*)d_in[2];
    const int*   bi = (const int*)d_in[3];
    float* out = (float*)d_out;

    gather_kernel<<<(NS + 255) / 256, 256>>>(a, b, ai, bi, out);
    dist_kernel<<<dim3(NIB, NKCH), TPB>>>(out);
}